// round 3
// baseline (speedup 1.0000x reference)
#include <cuda_runtime.h>
#include <cstddef>

// Problem constants (fixed by setup_inputs)
#define NSTEP 730
#define NGRID 1000
#define MUV   8
#define PRECS_F 1e-5f
#define PSTR ((size_t)NGRID * 13 * MUV)   // per-timestep param stride (elements)

__constant__ float d_LB[13] = {1.0f, 50.0f, 0.05f, 0.01f, 0.001f, 0.2f, 0.0f, 0.0f, -2.5f, 0.5f, 0.0f, 0.0f, 0.3f};
__constant__ float d_UB[13] = {6.0f, 1000.0f, 0.9f, 0.5f, 0.2f, 1.0f, 10.0f, 100.0f, 2.5f, 10.0f, 0.1f, 0.2f, 5.0f};

static __device__ __forceinline__ unsigned vary_mask(const int* tdlst, int ntd) {
    unsigned mask = 0u;
    for (int i = 0; i < ntd; ++i) {
        int v = (tdlst[i] - 1) % 13;
        if (v < 0) v += 13;
        mask |= 1u << v;
    }
    return mask;
}

// Lean HBV step: critical SM-chain shortened algebraically.
//   SM - max(SM-FC,0)            == min(SM, FC)
//   SM_mid = (SM + rt) - rt*sw   (SM+rt computed off-chain during first pow)
//   SM3 = max(SM2 - min(SM2, e), PRECS) == max(SM2 - e, PRECS)   (e >= 0)
static __device__ __forceinline__ float hbv_step_fast(
    float P, float T, float ET,
    float BETA, float BETAET,
    float FC, float K0, float K1, float K2, float PERCc, float UZL,
    float TT, float CFMAX, float CFRCF, float CWH,
    float invFC, float invLPFC,
    float& SP, float& MW, float& SM, float& SUZ, float& SLZ)
{
    // First pow depends only on carried SM -> starts immediately.
    float w  = __powf(SM * invFC, BETA);
    float sw = fminf(w, 1.0f);           // clip upper (w >= 0 always)

    // Snow chain overlaps the pow latency.
    float RAIN = (T >= TT) ? P : 0.0f;
    float SNOW = P - RAIN;
    float SPl  = SP + SNOW;
    float melt = fminf(fmaxf(CFMAX * (T - TT), 0.0f), SPl);
    float MWl  = MW + melt;
    SPl -= melt;
    float refr = fminf(fmaxf(CFRCF * (TT - T), 0.0f), MWl);
    SPl += refr; MWl -= refr;
    float tosoil = fmaxf(MWl - CWH * SPl, 0.0f);
    MW = MWl - tosoil;
    SP = SPl;

    float rt   = RAIN + tosoil;
    float SMrt = SM + rt;                // ready before pow completes
    float recharge = rt * sw;
    float SMm  = SMrt - recharge;
    float SM2  = fminf(SMm, FC);
    float excess = SMm - SM2;
    float e2 = __powf(SM2 * invLPFC, BETAET);
    float ef = fminf(e2, 1.0f);
    SM = fmaxf(fmaf(-ET, ef, SM2), PRECS_F);

    // Runoff chain (shorter, overlaps SM chain of next step)
    float SUZl = SUZ + recharge + excess;
    float PERC = fminf(SUZl, PERCc);
    SUZl -= PERC;
    float Q0 = K0 * fmaxf(SUZl - UZL, 0.0f);
    SUZl -= Q0;
    float Q1 = K1 * SUZl;
    SUZ = SUZl - Q1;
    float SLZl = SLZ + PERC;
    float Q2 = K2 * SLZl;
    SLZ = SLZl - Q2;
    return Q0 + Q1 + Q2;
}

// Original-form step for the generic fallback path.
static __device__ __forceinline__ float hbv_step_ref(
    float P, float T, float ET,
    float BETA, float FC, float K0, float K1, float K2, float LP,
    float PERCc, float UZL, float TT, float CFMAX, float CFRCFMAX,
    float CWH, float BETAET, float invFC, float invLPFC,
    float& SP, float& MW, float& SM, float& SUZ, float& SLZ)
{
    float rm   = (T >= TT) ? 1.0f : 0.0f;
    float RAIN = P * rm;
    float SNOW = P - RAIN;
    SP += SNOW;
    float melt = fminf(fmaxf(CFMAX * (T - TT), 0.0f), SP);
    MW += melt; SP -= melt;
    float refr = fminf(fmaxf(CFRCFMAX * (TT - T), 0.0f), MW);
    SP += refr; MW -= refr;
    float tosoil = fmaxf(MW - CWH * SP, 0.0f);
    MW -= tosoil;
    float sw = __saturatef(__powf(SM * invFC, BETA));
    float recharge = (RAIN + tosoil) * sw;
    SM = SM + RAIN + tosoil - recharge;
    float excess = fmaxf(SM - FC, 0.0f);
    SM -= excess;
    float ef = __saturatef(__powf(SM * invLPFC, BETAET));
    float ETact = fminf(SM, ET * ef);
    SM = fmaxf(SM - ETact, PRECS_F);
    SUZ = SUZ + recharge + excess;
    float PERC = fminf(SUZ, PERCc);
    SUZ -= PERC;
    float Q0 = K0 * fmaxf(SUZ - UZL, 0.0f);
    SUZ -= Q0;
    float Q1 = K1 * SUZ;
    SUZ -= Q1;
    SLZ += PERC;
    float Q2 = K2 * SLZ;
    SLZ -= Q2;
    return Q0 + Q1 + Q2;
}

// ---------------------------------------------------------------------------
// Single merged kernel. Fast path (varying mask == {BETA, BETAET}): 2 chains
// per thread for ILP, float2 param loads, double-buffered prefetch (UNR=2).
// Generic path otherwise.
// ---------------------------------------------------------------------------
__global__ void __launch_bounds__(32, 8) hbv_kernel(
    const float* __restrict__ x,      // (NSTEP, NGRID, 3)
    const float* __restrict__ par,    // (NSTEP, NGRID, 13, MUV)
    const int*   __restrict__ staindp,
    const int*   __restrict__ tdlst, int ntd,
    const int*   __restrict__ mup,
    float*       __restrict__ out)    // (NSTEP, NGRID, 1)
{
    unsigned mask = vary_mask(tdlst, ntd);
    int tid = blockIdx.x * 32 + threadIdx.x;

    if (mask == ((1u << 0) | (1u << 12))) {
        // ------------------ fast path: NCH=2 chains per thread ---------------
        if (blockIdx.x >= 125) return;     // 125 blocks * 32 = 4000 threads
        int g  = tid >> 2;                 // 0..999 (4 threads per grid)
        int mb = (tid & 3) * 2;            // mu base: 0,2,4,6

        int   staind = *staindp;
        float invmu  = 1.0f / (float)(*mup);

        const float* pb  = par + (size_t)g * 13 * MUV + mb;
        const float* pst = pb + (size_t)staind * PSTR;

        // Constant (frozen at staind) transformed parameters, 2 chains each.
        float FC[2], K0[2], K1[2], K2[2], PERCc[2], UZL[2], TT[2];
        float CFMAX[2], CFRCF[2], CWH[2], invFC[2], invLPFC[2];
        {
            float2 q;
            q = __ldg((const float2*)(pst + 1 * MUV));  FC[0] = 50.0f + q.x * 950.0f;   FC[1] = 50.0f + q.y * 950.0f;
            q = __ldg((const float2*)(pst + 2 * MUV));  K0[0] = 0.05f + q.x * 0.85f;    K0[1] = 0.05f + q.y * 0.85f;
            q = __ldg((const float2*)(pst + 3 * MUV));  K1[0] = 0.01f + q.x * 0.49f;    K1[1] = 0.01f + q.y * 0.49f;
            q = __ldg((const float2*)(pst + 4 * MUV));  K2[0] = 0.001f + q.x * 0.199f;  K2[1] = 0.001f + q.y * 0.199f;
            float LP0, LP1;
            q = __ldg((const float2*)(pst + 5 * MUV));  LP0 = 0.2f + q.x * 0.8f;        LP1 = 0.2f + q.y * 0.8f;
            q = __ldg((const float2*)(pst + 6 * MUV));  PERCc[0] = q.x * 10.0f;         PERCc[1] = q.y * 10.0f;
            q = __ldg((const float2*)(pst + 7 * MUV));  UZL[0] = q.x * 100.0f;          UZL[1] = q.y * 100.0f;
            q = __ldg((const float2*)(pst + 8 * MUV));  TT[0] = -2.5f + q.x * 5.0f;     TT[1] = -2.5f + q.y * 5.0f;
            q = __ldg((const float2*)(pst + 9 * MUV));  CFMAX[0] = 0.5f + q.x * 9.5f;   CFMAX[1] = 0.5f + q.y * 9.5f;
            q = __ldg((const float2*)(pst + 10 * MUV)); CFRCF[0] = q.x * 0.1f * CFMAX[0]; CFRCF[1] = q.y * 0.1f * CFMAX[1];
            q = __ldg((const float2*)(pst + 11 * MUV)); CWH[0] = q.x * 0.2f;            CWH[1] = q.y * 0.2f;
            invFC[0]   = __fdividef(1.0f, FC[0]);
            invFC[1]   = __fdividef(1.0f, FC[1]);
            invLPFC[0] = __fdividef(1.0f, LP0 * FC[0]);
            invLPFC[1] = __fdividef(1.0f, LP1 * FC[1]);
        }

        float SP[2]  = {1e-3f, 1e-3f}, MW[2] = {1e-3f, 1e-3f}, SM[2] = {1e-3f, 1e-3f};
        float SUZ[2] = {1e-3f, 1e-3f}, SLZ[2] = {1e-3f, 1e-3f};

        const float* xb = x + (size_t)g * 3;

        // Double-buffered prefetch of the 2 time-varying params + forcings.
        float  bP[2], bT[2], bE[2];
        float2 bB[2], bBE[2];
        #pragma unroll
        for (int u = 0; u < 2; ++u) {
            const float* xp = xb + (size_t)u * NGRID * 3;
            bP[u] = __ldg(xp); bT[u] = __ldg(xp + 1); bE[u] = __ldg(xp + 2);
            const float* pp = pb + (size_t)u * PSTR;
            bB[u]  = __ldg((const float2*)(pp));
            bBE[u] = __ldg((const float2*)(pp + 12 * MUV));
        }

        int t = 0;
        for (int grp = 0; grp < NSTEP / 2; ++grp) {     // 365 groups of 2
            float  cP[2]  = {bP[0], bP[1]},  cT[2] = {bT[0], bT[1]}, cE[2] = {bE[0], bE[1]};
            float2 cB[2]  = {bB[0], bB[1]},  cBE[2] = {bBE[0], bBE[1]};
            if (grp + 1 < NSTEP / 2) {
                #pragma unroll
                for (int u = 0; u < 2; ++u) {
                    int tn = t + 2 + u;
                    const float* xp = xb + (size_t)tn * NGRID * 3;
                    bP[u] = __ldg(xp); bT[u] = __ldg(xp + 1); bE[u] = __ldg(xp + 2);
                    const float* pp = pb + (size_t)tn * PSTR;
                    bB[u]  = __ldg((const float2*)(pp));
                    bBE[u] = __ldg((const float2*)(pp + 12 * MUV));
                }
            }
            #pragma unroll
            for (int u = 0; u < 2; ++u) {
                float B0  = 1.0f + cB[u].x * 5.0f;
                float B1  = 1.0f + cB[u].y * 5.0f;
                float BE0 = 0.3f + cBE[u].x * 4.7f;
                float BE1 = 0.3f + cBE[u].y * 4.7f;
                float q0 = hbv_step_fast(cP[u], cT[u], cE[u], B0, BE0,
                                         FC[0], K0[0], K1[0], K2[0], PERCc[0], UZL[0],
                                         TT[0], CFMAX[0], CFRCF[0], CWH[0],
                                         invFC[0], invLPFC[0],
                                         SP[0], MW[0], SM[0], SUZ[0], SLZ[0]);
                float q1 = hbv_step_fast(cP[u], cT[u], cE[u], B1, BE1,
                                         FC[1], K0[1], K1[1], K2[1], PERCc[1], UZL[1],
                                         TT[1], CFMAX[1], CFRCF[1], CWH[1],
                                         invFC[1], invLPFC[1],
                                         SP[1], MW[1], SM[1], SUZ[1], SLZ[1]);
                float qs = q0 + q1;
                // 4 consecutive lanes share the same grid -> 2-level xor reduce.
                qs += __shfl_xor_sync(0xffffffffu, qs, 1);
                qs += __shfl_xor_sync(0xffffffffu, qs, 2);
                if ((tid & 3) == 0) out[(size_t)(t + u) * NGRID + g] = qs * invmu;
            }
            t += 2;
        }
        return;
    }

    // ------------------------- generic fallback -----------------------------
    {
        int g = tid >> 3;
        int m = tid & 7;
        if (g >= NGRID) return;

        int   staind = *staindp;
        float invmu  = 1.0f / (float)(*mup);

        const float* pb  = par + (size_t)g * 13 * MUV + m;
        const float* pst = pb + (size_t)staind * PSTR;

        float basep[13];
        #pragma unroll
        for (int p = 0; p < 13; ++p)
            basep[p] = d_LB[p] + __ldg(pst + p * MUV) * (d_UB[p] - d_LB[p]);

        float SP = 1e-3f, MW = 1e-3f, SM = 1e-3f, SUZ = 1e-3f, SLZ = 1e-3f;
        const float* xb = x + (size_t)g * 3;

        for (int t = 0; t < NSTEP; ++t) {
            float pv[13];
            const float* pp = pb + (size_t)t * PSTR;
            #pragma unroll
            for (int p = 0; p < 13; ++p) {
                if ((mask >> p) & 1u)
                    pv[p] = d_LB[p] + __ldg(pp + p * MUV) * (d_UB[p] - d_LB[p]);
                else
                    pv[p] = basep[p];
            }
            const float* xp = xb + (size_t)t * NGRID * 3;
            float P = __ldg(xp + 0), T = __ldg(xp + 1), ET = __ldg(xp + 2);

            float invFC   = __fdividef(1.0f, pv[1]);
            float invLPFC = __fdividef(1.0f, pv[5] * pv[1]);
            float Q = hbv_step_ref(P, T, ET,
                                   pv[0], pv[1], pv[2], pv[3], pv[4], pv[5], pv[6],
                                   pv[7], pv[8], pv[9], pv[10] * pv[9], pv[11], pv[12],
                                   invFC, invLPFC,
                                   SP, MW, SM, SUZ, SLZ);
            Q += __shfl_xor_sync(0xffffffffu, Q, 1);
            Q += __shfl_xor_sync(0xffffffffu, Q, 2);
            Q += __shfl_xor_sync(0xffffffffu, Q, 4);
            if (m == 0) out[(size_t)t * NGRID + g] = Q * invmu;
        }
    }
}

extern "C" void kernel_launch(void* const* d_in, const int* in_sizes, int n_in,
                              void* d_out, int out_size) {
    const float* x      = (const float*)d_in[0];
    const float* par    = (const float*)d_in[1];
    const int*   staind = (const int*)d_in[2];
    const int*   tdlst  = (const int*)d_in[3];
    const int*   mu     = (const int*)d_in[4];
    float*       out    = (float*)d_out;
    int ntd = in_sizes[3];

    // 250 blocks covers generic path (8000 chains); fast path uses first 125.
    hbv_kernel<<<250, 32>>>(x, par, staind, tdlst, ntd, mu, out);
}

// round 4
// speedup vs baseline: 1.8170x; 1.8170x over previous
#include <cuda_runtime.h>
#include <cstddef>

#define NSTEP 730
#define NGRID 1000
#define MUV   8
#define PRECS_F 1e-5f
#define PSTR ((size_t)NGRID * 13 * MUV)   // 104000 elements per timestep
#define XSTR ((size_t)NGRID * 3)          // 3000 elements per timestep

__constant__ float d_LB[13] = {1.0f, 50.0f, 0.05f, 0.01f, 0.001f, 0.2f, 0.0f, 0.0f, -2.5f, 0.5f, 0.0f, 0.0f, 0.3f};
__constant__ float d_UB[13] = {6.0f, 1000.0f, 0.9f, 0.5f, 0.2f, 1.0f, 10.0f, 100.0f, 2.5f, 10.0f, 0.1f, 0.2f, 5.0f};

static __device__ __forceinline__ unsigned vary_mask(const int* tdlst, int ntd) {
    unsigned mask = 0u;
    for (int i = 0; i < ntd; ++i) {
        int v = (tdlst[i] - 1) % 13;
        if (v < 0) v += 13;
        mask |= 1u << v;
    }
    return mask;
}

// ---------------------------------------------------------------------------
// Fast-path state + frozen params bundle
// ---------------------------------------------------------------------------
struct HbvConst {
    float FC, K0, K1, K2, PERCc, UZL, TT, CFMAX, CFRCF, CWH, invFC, invLPFC;
};

// Minimal-critical-path HBV step. Exact-equivalent transforms:
//   SM1 = SMrt - rt*min(w,1) = max(fma(-rt,w,SMrt), SM)          (rt>=0)
//   SM2 = min(SM1, FC)              [excess removal]
//   recharge + excess = SMrt - SM2  [single FADD for SUZ input]
//   SM3 = max(SM2 - min(ET*e2, ET), PRECS)
//       = max(max(fma(-ET,e2,SM2), SM2-ET), PRECS)
static __device__ __forceinline__ float hbv_step_lean(
    float P, float T, float ET, float BETA, float BETAET, const HbvConst& c,
    float& SP, float& MW, float& SM, float& SUZ, float& SLZ)
{
    // pow #1 starts immediately off carried SM
    float w = __powf(SM * c.invFC, BETA);

    // snow chain (parallel with pow #1)
    float RAIN = (T >= c.TT) ? P : 0.0f;
    float SNOW = P - RAIN;
    float SPl  = SP + SNOW;
    float melt = fminf(fmaxf(c.CFMAX * (T - c.TT), 0.0f), SPl);
    float MWl  = MW + melt;
    SPl -= melt;
    float refr = fminf(fmaxf(c.CFRCF * (c.TT - T), 0.0f), MWl);
    SPl += refr; MWl -= refr;
    float tosoil = fmaxf(MWl - c.CWH * SPl, 0.0f);
    MW = MWl - tosoil;
    SP = SPl;

    float rt   = RAIN + tosoil;
    float SMrt = SM + rt;

    float SM1 = fmaxf(__fmaf_rn(-rt, w, SMrt), SM);
    float SM2 = fminf(SM1, c.FC);

    // pow #2
    float e2  = __powf(SM2 * c.invLPFC, BETAET);
    float SM2mET = SM2 - ET;                          // off-chain
    SM = fmaxf(fmaxf(__fmaf_rn(-ET, e2, SM2), SM2mET), PRECS_F);

    // runoff chain (slack; recharge+excess == SMrt - SM2)
    float SUZ1 = SUZ + (SMrt - SM2);
    float PERC = fminf(SUZ1, c.PERCc);
    float SUZ2 = SUZ1 - PERC;
    float Q0   = c.K0 * fmaxf(SUZ2 - c.UZL, 0.0f);
    float SUZ3 = SUZ2 - Q0;
    float Q1   = c.K1 * SUZ3;
    SUZ = SUZ3 - Q1;
    float SLZ1 = SLZ + PERC;
    float Q2   = c.K2 * SLZ1;
    SLZ = SLZ1 - Q2;
    return Q0 + Q1 + Q2;
}

// Process one group of 5 steps from buffer `b*`, then refill that buffer with
// timesteps t+10 .. t+14 (clamped) => 10-step prefetch distance (~900 cyc).
static __device__ __forceinline__ void hbv_group5(
    float (&bP)[5], float (&bT)[5], float (&bE)[5], float (&bB)[5], float (&bBE)[5],
    int t, const float* __restrict__ xb, const float* __restrict__ pb,
    const HbvConst& c, float invmu, int g, int m,
    float& SP, float& MW, float& SM, float& SUZ, float& SLZ,
    float* __restrict__ out)
{
    #pragma unroll
    for (int u = 0; u < 5; ++u) {
        float P = bP[u], T = bT[u], E = bE[u];
        float BETA   = 1.0f + bB[u]  * 5.0f;
        float BETAET = 0.3f + bBE[u] * 4.7f;

        // prefetch slot u for t+10+u (clamped; garbage values never used)
        int tp = t + 10 + u; tp = (tp > NSTEP - 1) ? (NSTEP - 1) : tp;
        const float* xp = xb + (size_t)tp * XSTR;
        const float* pp = pb + (size_t)tp * PSTR;
        bP[u]  = __ldg(xp);
        bT[u]  = __ldg(xp + 1);
        bE[u]  = __ldg(xp + 2);
        bB[u]  = __ldg(pp);             // BETA raw (param 0)
        bBE[u] = __ldg(pp + 12 * MUV);  // BETAET raw (param 12)

        float Q = hbv_step_lean(P, T, E, BETA, BETAET, c, SP, MW, SM, SUZ, SLZ);

        Q += __shfl_xor_sync(0xffffffffu, Q, 1);
        Q += __shfl_xor_sync(0xffffffffu, Q, 2);
        Q += __shfl_xor_sync(0xffffffffu, Q, 4);
        if (m == 0) out[(size_t)(t + u) * NGRID + g] = Q * invmu;
    }
}

// Original-form step for the generic fallback path.
static __device__ __forceinline__ float hbv_step_ref(
    float P, float T, float ET,
    float BETA, float FC, float K0, float K1, float K2, float LP,
    float PERCc, float UZL, float TT, float CFMAX, float CFRCFMAX,
    float CWH, float BETAET, float invFC, float invLPFC,
    float& SP, float& MW, float& SM, float& SUZ, float& SLZ)
{
    float rm   = (T >= TT) ? 1.0f : 0.0f;
    float RAIN = P * rm;
    float SNOW = P - RAIN;
    SP += SNOW;
    float melt = fminf(fmaxf(CFMAX * (T - TT), 0.0f), SP);
    MW += melt; SP -= melt;
    float refr = fminf(fmaxf(CFRCFMAX * (TT - T), 0.0f), MW);
    SP += refr; MW -= refr;
    float tosoil = fmaxf(MW - CWH * SP, 0.0f);
    MW -= tosoil;
    float sw = __saturatef(__powf(SM * invFC, BETA));
    float recharge = (RAIN + tosoil) * sw;
    SM = SM + RAIN + tosoil - recharge;
    float excess = fmaxf(SM - FC, 0.0f);
    SM -= excess;
    float ef = __saturatef(__powf(SM * invLPFC, BETAET));
    float ETact = fminf(SM, ET * ef);
    SM = fmaxf(SM - ETact, PRECS_F);
    SUZ = SUZ + recharge + excess;
    float PERC = fminf(SUZ, PERCc);
    SUZ -= PERC;
    float Q0 = K0 * fmaxf(SUZ - UZL, 0.0f);
    SUZ -= Q0;
    float Q1 = K1 * SUZ;
    SUZ -= Q1;
    SLZ += PERC;
    float Q2 = K2 * SLZ;
    SLZ -= Q2;
    return Q0 + Q1 + Q2;
}

// ---------------------------------------------------------------------------
// Merged kernel. Fast path: 1 chain/thread, 250 warps, lean step, 10-step
// prefetch. Generic path: arbitrary varying-mask fallback.
// ---------------------------------------------------------------------------
__global__ void __launch_bounds__(32) hbv_kernel(
    const float* __restrict__ x,      // (NSTEP, NGRID, 3)
    const float* __restrict__ par,    // (NSTEP, NGRID, 13, MUV)
    const int*   __restrict__ staindp,
    const int*   __restrict__ tdlst, int ntd,
    const int*   __restrict__ mup,
    float*       __restrict__ out)    // (NSTEP, NGRID, 1)
{
    unsigned mask = vary_mask(tdlst, ntd);
    int tid = blockIdx.x * 32 + threadIdx.x;
    int g = tid >> 3;          // 0..999
    int m = tid & 7;           // mu index
    if (g >= NGRID) return;

    int   staind = *staindp;
    float invmu  = 1.0f / (float)(*mup);

    const float* pb  = par + (size_t)g * 13 * MUV + m;
    const float* pst = pb + (size_t)staind * PSTR;
    const float* xb  = x + (size_t)g * 3;

    if (mask == ((1u << 0) | (1u << 12))) {
        // ------------------------- fast path --------------------------------
        HbvConst c;
        c.FC    =  50.0f  + __ldg(pst + 1 * MUV)  * 950.0f;
        c.K0    =  0.05f  + __ldg(pst + 2 * MUV)  * 0.85f;
        c.K1    =  0.01f  + __ldg(pst + 3 * MUV)  * 0.49f;
        c.K2    =  0.001f + __ldg(pst + 4 * MUV)  * 0.199f;
        float LP =  0.2f  + __ldg(pst + 5 * MUV)  * 0.8f;
        c.PERCc =           __ldg(pst + 6 * MUV)  * 10.0f;
        c.UZL   =           __ldg(pst + 7 * MUV)  * 100.0f;
        c.TT    = -2.5f   + __ldg(pst + 8 * MUV)  * 5.0f;
        c.CFMAX =  0.5f   + __ldg(pst + 9 * MUV)  * 9.5f;
        c.CFRCF =           __ldg(pst + 10 * MUV) * 0.1f * c.CFMAX;
        c.CWH   =           __ldg(pst + 11 * MUV) * 0.2f;
        c.invFC   = __fdividef(1.0f, c.FC);
        c.invLPFC = __fdividef(1.0f, LP * c.FC);

        float SP = 1e-3f, MW = 1e-3f, SM = 1e-3f, SUZ = 1e-3f, SLZ = 1e-3f;

        // Two 5-step buffers: A holds t..t+4, B holds t+5..t+9.
        float aP[5], aT[5], aE[5], aB[5], aBE[5];
        float bP[5], bT[5], bE[5], bB[5], bBE[5];
        #pragma unroll
        for (int u = 0; u < 5; ++u) {
            const float* xp = xb + (size_t)u * XSTR;
            aP[u] = __ldg(xp); aT[u] = __ldg(xp + 1); aE[u] = __ldg(xp + 2);
            const float* pp = pb + (size_t)u * PSTR;
            aB[u] = __ldg(pp); aBE[u] = __ldg(pp + 12 * MUV);
        }
        #pragma unroll
        for (int u = 0; u < 5; ++u) {
            const float* xp = xb + (size_t)(5 + u) * XSTR;
            bP[u] = __ldg(xp); bT[u] = __ldg(xp + 1); bE[u] = __ldg(xp + 2);
            const float* pp = pb + (size_t)(5 + u) * PSTR;
            bB[u] = __ldg(pp); bBE[u] = __ldg(pp + 12 * MUV);
        }

        int t = 0;
        #pragma unroll 1
        for (int g2 = 0; g2 < NSTEP / 10; ++g2) {   // 73 iterations of 10 steps
            hbv_group5(aP, aT, aE, aB, aBE, t, xb, pb, c, invmu, g, m,
                       SP, MW, SM, SUZ, SLZ, out);
            t += 5;
            hbv_group5(bP, bT, bE, bB, bBE, t, xb, pb, c, invmu, g, m,
                       SP, MW, SM, SUZ, SLZ, out);
            t += 5;
        }
        return;
    }

    // ------------------------- generic fallback -----------------------------
    {
        float basep[13];
        #pragma unroll
        for (int p = 0; p < 13; ++p)
            basep[p] = d_LB[p] + __ldg(pst + p * MUV) * (d_UB[p] - d_LB[p]);

        float SP = 1e-3f, MW = 1e-3f, SM = 1e-3f, SUZ = 1e-3f, SLZ = 1e-3f;

        for (int t = 0; t < NSTEP; ++t) {
            float pv[13];
            const float* pp = pb + (size_t)t * PSTR;
            #pragma unroll
            for (int p = 0; p < 13; ++p) {
                if ((mask >> p) & 1u)
                    pv[p] = d_LB[p] + __ldg(pp + p * MUV) * (d_UB[p] - d_LB[p]);
                else
                    pv[p] = basep[p];
            }
            const float* xp = xb + (size_t)t * XSTR;
            float P = __ldg(xp + 0), T = __ldg(xp + 1), ET = __ldg(xp + 2);

            float invFC   = __fdividef(1.0f, pv[1]);
            float invLPFC = __fdividef(1.0f, pv[5] * pv[1]);
            float Q = hbv_step_ref(P, T, ET,
                                   pv[0], pv[1], pv[2], pv[3], pv[4], pv[5], pv[6],
                                   pv[7], pv[8], pv[9], pv[10] * pv[9], pv[11], pv[12],
                                   invFC, invLPFC,
                                   SP, MW, SM, SUZ, SLZ);
            Q += __shfl_xor_sync(0xffffffffu, Q, 1);
            Q += __shfl_xor_sync(0xffffffffu, Q, 2);
            Q += __shfl_xor_sync(0xffffffffu, Q, 4);
            if (m == 0) out[(size_t)t * NGRID + g] = Q * invmu;
        }
    }
}

extern "C" void kernel_launch(void* const* d_in, const int* in_sizes, int n_in,
                              void* d_out, int out_size) {
    const float* x      = (const float*)d_in[0];
    const float* par    = (const float*)d_in[1];
    const int*   staind = (const int*)d_in[2];
    const int*   tdlst  = (const int*)d_in[3];
    const int*   mu     = (const int*)d_in[4];
    float*       out    = (float*)d_out;
    int ntd = in_sizes[3];

    hbv_kernel<<<250, 32>>>(x, par, staind, tdlst, ntd, mu, out);
}